// round 16
// baseline (speedup 1.0000x reference)
#include <cuda_runtime.h>
#include <cuda_fp16.h>
#include <cstdint>

#define TOKENS 8192
#define INF    4096
#define OUTF   4096

// Scratch device globals (no allocations allowed).
__device__ __half g_Wh[(size_t)OUTF * INF];    // 32 MB
__device__ __half g_Xh[(size_t)TOKENS * INF];  // 64 MB
__device__ int g_w_is_i8;

// ---------------------------------------------------------------------------
// mbarrier helpers (plain sm_80/sm_90 PTX — legal under compute_100)
// ---------------------------------------------------------------------------
#define MBAR_INIT(a, n) \
    asm volatile("mbarrier.init.shared.b64 [%0], %1;" :: "r"(a), "r"(n) : "memory")
#define MBAR_WAIT(a, ph) do { \
    uint32_t _m = (a), _p = (ph), _d; \
    asm volatile("{ .reg .pred p; mbarrier.try_wait.parity.shared.b64 p, [%1], %2; selp.b32 %0,1,0,p; }" \
                 : "=r"(_d) : "r"(_m), "r"(_p) : "memory"); \
    if (!_d) { \
        asm volatile("{ .reg .pred P; WL_%=: mbarrier.try_wait.parity.shared.b64 P, [%0], %1; " \
                     "@P bra.uni WD_%=; bra.uni WL_%=; WD_%=: }" :: "r"(_m), "r"(_p) : "memory"); \
    } } while (0)
#define MBAR_ARRIVE(a) \
    asm volatile("{ .reg .b64 t; mbarrier.arrive.shared.b64 t, [%0]; }" :: "r"(a) : "memory")
#define CPASYNC_MBAR_ARRIVE_NOINC(a) \
    asm volatile("cp.async.mbarrier.arrive.noinc.shared.b64 [%0];" :: "r"(a) : "memory")

// ---------------------------------------------------------------------------
// Preprocess 0: weight dtype detection (int8 vs int32 delivery)
// ---------------------------------------------------------------------------
__global__ void detect_w_kernel(const int* __restrict__ w32) {
    __shared__ int bad;
    if (threadIdx.x == 0) bad = 0;
    __syncthreads();
    for (int i = threadIdx.x; i < 4096; i += 256) {
        int v = w32[(size_t)i * 1000 + 3];
        if (v < -2 || v > 1) bad = 1;
    }
    __syncthreads();
    if (threadIdx.x == 0) g_w_is_i8 = bad;
}

// ---------------------------------------------------------------------------
// Preprocess 1: weights {-2,-1,0,1} (int8 OR int32) -> fp16 (exact)
// ---------------------------------------------------------------------------
__global__ void convert_w_kernel(const void* __restrict__ wq) {
    size_t i = (size_t)blockIdx.x * blockDim.x + threadIdx.x;
    size_t total4 = (size_t)OUTF * INF / 4;
    if (i >= total4) return;
    int v0, v1, v2, v3;
    if (g_w_is_i8) {
        char4 v = reinterpret_cast<const char4*>(wq)[i];
        v0 = v.x; v1 = v.y; v2 = v.z; v3 = v.w;
    } else {
        int4 v = reinterpret_cast<const int4*>(wq)[i];
        v0 = v.x; v1 = v.y; v2 = v.z; v3 = v.w;
    }
    __half2 p0, p1;
    p0.x = __float2half_rn((float)v0); p0.y = __float2half_rn((float)v1);
    p1.x = __float2half_rn((float)v2); p1.y = __float2half_rn((float)v3);
    reinterpret_cast<__half2*>(g_Wh)[i * 2 + 0] = p0;
    reinterpret_cast<__half2*>(g_Wh)[i * 2 + 1] = p1;
}

// ---------------------------------------------------------------------------
// Preprocess 2: fp32 x -> fp16
// ---------------------------------------------------------------------------
__global__ void convert_x_kernel(const float* __restrict__ x) {
    size_t i = (size_t)blockIdx.x * blockDim.x + threadIdx.x;
    size_t total4 = (size_t)TOKENS * INF / 4;
    if (i >= total4) return;
    float4 v = reinterpret_cast<const float4*>(x)[i];
    __half2 p0, p1;
    p0.x = __float2half_rn(v.x); p0.y = __float2half_rn(v.y);
    p1.x = __float2half_rn(v.z); p1.y = __float2half_rn(v.w);
    reinterpret_cast<__half2*>(g_Xh)[i * 2 + 0] = p0;
    reinterpret_cast<__half2*>(g_Xh)[i * 2 + 1] = p1;
}

// ---------------------------------------------------------------------------
// GEMM: C = Xh @ Wh^T + epilogue.  BM=256 BN=128 BK=64, 256 thr, 1 CTA/SM.
// mbarrier full/empty pipeline, no __syncthreads in loop.  All cross-warp
// waits (empty) and the 12-op cp.async refill are BACK-LOADED after the
// iteration's 128 mma issues, so a leading warp fills the tensor queue
// before it can convoy on the block-wide laggard.  Empty barriers are
// per-warp (init 8, lane-0 arrives).
// ---------------------------------------------------------------------------
#define BM 256
#define BN 128
#define BK 64
#define KT (INF / BK)        // 64 outer iterations
#define STAGES 3
#define PB   144             // smem row pitch bytes
#define A_STG (BM * PB)      // 36864
#define B_STG (BN * PB)      // 18432
#define STG   (A_STG + B_STG)              // 55296
#define BAR_OFF (STAGES * STG)             // barrier area
#define SMEM_TOTAL (BAR_OFF + 64)          // 165952 B

// Issue 3 of the 12 per-thread cp.asyncs for this chunk (part j of 4).
__device__ __forceinline__ void load_part(uint32_t sbase,
                                          const __half* Ag, const __half* Bg,
                                          int kt, int stage, int tid, int j) {
    const int kk = kt * BK;
    const uint32_t d0 = sbase + stage * STG;
#pragma unroll
    for (int q = 0; q < 3; q++) {
        int i = j * 3 + q;
        int c = tid + i * 256;
        const void* src;
        uint32_t dst;
        if (i < 8) {                         // A: 256 rows x 8 segs = 2048 chunks
            int row = c >> 3, seg = c & 7;
            src = Ag + (size_t)row * INF + kk + seg * 8;
            dst = d0 + row * PB + seg * 16;
        } else {                             // B: 128 rows x 8 segs = 1024 chunks
            int o = c - 2048;
            int row = o >> 3, seg = o & 7;
            src = Bg + (size_t)row * INF + kk + seg * 8;
            dst = d0 + A_STG + row * PB + seg * 16;
        }
        asm volatile("cp.async.cg.shared.global [%0], [%1], 16;\n" :: "r"(dst), "l"(src));
    }
}

// 8-ldmatrix fragment fetch for one ks-slice of one stage.
#define FRAG_FETCH(AF, BF, aB, bB, kOff)                                      \
    do {                                                                      \
        _Pragma("unroll")                                                     \
        for (int mt_ = 0; mt_ < 4; mt_++) {                                   \
            asm volatile(                                                     \
                "ldmatrix.sync.aligned.m8n8.x4.shared.b16 {%0,%1,%2,%3}, [%4];\n" \
                : "=r"((AF)[mt_][0]), "=r"((AF)[mt_][1]),                    \
                  "=r"((AF)[mt_][2]), "=r"((AF)[mt_][3])                     \
                : "r"((aB) + (uint32_t)(mt_ * 16) * PB + (kOff)));           \
        }                                                                     \
        _Pragma("unroll")                                                     \
        for (int np_ = 0; np_ < 4; np_++) {                                   \
            asm volatile(                                                     \
                "ldmatrix.sync.aligned.m8n8.x4.shared.b16 {%0,%1,%2,%3}, [%4];\n" \
                : "=r"((BF)[np_ * 2][0]), "=r"((BF)[np_ * 2][1]),            \
                  "=r"((BF)[np_ * 2 + 1][0]), "=r"((BF)[np_ * 2 + 1][1])     \
                : "r"((bB) + (uint32_t)(np_ * 16) * PB + (kOff)));           \
        }                                                                     \
    } while (0)

__global__ __launch_bounds__(256, 1) void gemm_kernel(const float* __restrict__ scale_p,
                                                      const float* __restrict__ bias,
                                                      float* __restrict__ out) {
    extern __shared__ char smem[];
    uint32_t sbase;
    asm("{ .reg .u64 t; cvta.to.shared.u64 t, %1; cvt.u32.u64 %0, t; }"
        : "=r"(sbase) : "l"(smem));

    const int tid  = threadIdx.x;
    const int warp = tid >> 5;
    const int lane = tid & 31;
    const int wm   = warp >> 1;      // 4 m-warps: 64 rows each
    const int wn   = warp & 1;       // 2 n-warps: 64 cols each
    const int koff = (warp & 4) ? 2 : 0;   // ks stagger: warps 4-7 rotate by 2
    const int bm   = blockIdx.y * BM;
    const int bn   = blockIdx.x * BN;

    // full(s) at BAR_OFF + s*16 (count 256, cp.async noinc arrivals);
    // empty(s) at +8 (count 8, per-warp lane-0 arrivals).
    const uint32_t barB = sbase + BAR_OFF;
    if (tid == 0) {
#pragma unroll
        for (int s = 0; s < STAGES; s++) {
            MBAR_INIT(barB + s * 16, 256u);
            MBAR_INIT(barB + s * 16 + 8, 8u);
        }
    }
    __syncthreads();   // only barrier: after init

    const __half* Ag = g_Xh + (size_t)bm * INF;
    const __half* Bg = g_Wh + (size_t)bn * INF;

    const uint32_t aRowOff = (uint32_t)(wm * 64 + (lane & 15)) * PB + ((lane >> 4) << 3) * 2;
    const uint32_t bRowOff = (uint32_t)(wn * 64 + ((lane >> 4) << 3) + (lane & 7)) * PB
                             + (((lane >> 3) & 1) << 3) * 2;

    float acc[4][8][4];
#pragma unroll
    for (int mt = 0; mt < 4; mt++)
#pragma unroll
        for (int nt = 0; nt < 8; nt++)
#pragma unroll
            for (int r = 0; r < 4; r++) acc[mt][nt][r] = 0.0f;

    uint32_t af[2][4][4];
    uint32_t bf[2][8][2];
    uint32_t phF = 0, phE = 0;   // per-stage parity bits

    // Prologue: stages 0,1 <- chunks 0,1 (fresh stages, no empty wait)
#pragma unroll
    for (int j = 0; j < 4; j++) load_part(sbase, Ag, Bg, 0, 0, tid, j);
    CPASYNC_MBAR_ARRIVE_NOINC(barB + 0 * 16);
#pragma unroll
    for (int j = 0; j < 4; j++) load_part(sbase, Ag, Bg, 1, 1, tid, j);
    CPASYNC_MBAR_ARRIVE_NOINC(barB + 1 * 16);

#pragma unroll 1
    for (int kt = 0; kt < KT; kt++) {
        const int s = kt % STAGES;
        MBAR_WAIT(barB + s * 16, (phF >> s) & 1);
        phF ^= 1u << s;

        const uint32_t aBase = sbase + s * STG + aRowOff;
        const uint32_t bBase = sbase + s * STG + A_STG + bRowOff;

        // First fragment load: ks index rotated per warp half.
        {
            const uint32_t kOff = (uint32_t)((koff & 3) * 16) * 2;
            FRAG_FETCH(af[0], bf[0], aBase, bBase, kOff);
        }

        // Compute phase: 4 ks-steps, fragment double-buffered; no cross-warp
        // waits anywhere in here.
#pragma unroll
        for (int j = 0; j < 4; j++) {
            const int cur = j & 1;
            const int nxt = cur ^ 1;
            if (j < 3) {
                const uint32_t kOff = (uint32_t)(((j + 1 + koff) & 3) * 16) * 2;
                FRAG_FETCH(af[nxt], bf[nxt], aBase, bBase, kOff);
            }
#pragma unroll
            for (int mt = 0; mt < 4; mt++)
#pragma unroll
                for (int nt = 0; nt < 8; nt++) {
                    asm volatile(
                        "mma.sync.aligned.m16n8k16.row.col.f32.f16.f16.f32 "
                        "{%0,%1,%2,%3}, {%4,%5,%6,%7}, {%8,%9}, {%0,%1,%2,%3};\n"
                        : "+f"(acc[mt][nt][0]), "+f"(acc[mt][nt][1]),
                          "+f"(acc[mt][nt][2]), "+f"(acc[mt][nt][3])
                        : "r"(af[cur][mt][0]), "r"(af[cur][mt][1]),
                          "r"(af[cur][mt][2]), "r"(af[cur][mt][3]),
                          "r"(bf[cur][nt][0]), "r"(bf[cur][nt][1]));
                }
        }

        // Back-loaded producer phase: wait for the stage we will overwrite,
        // then issue the full 12-op refill and commit.  Tensor pipe drains
        // the just-issued mma queue while this warp sits here.
        if (kt + 2 < KT) {
            const int ls = (kt + 2) % STAGES;
            if (kt >= 1) {
                MBAR_WAIT(barB + ls * 16 + 8, (phE >> ls) & 1);
                phE ^= 1u << ls;
            }
#pragma unroll
            for (int j = 0; j < 4; j++) load_part(sbase, Ag, Bg, kt + 2, ls, tid, j);
            CPASYNC_MBAR_ARRIVE_NOINC(barB + ls * 16);
        }

        // Consumer: all smem reads of stage s done (ldmatrix is warp-
        // converged); lane 0 arrives on the per-warp empty barrier.
        if (kt + 3 < KT && lane == 0) {
            MBAR_ARRIVE(barB + s * 16 + 8);
        }
    }

    // Epilogue: y = scale * acc + bias
    const float s = __ldg(scale_p);
#pragma unroll
    for (int mt = 0; mt < 4; mt++) {
#pragma unroll
        for (int nt = 0; nt < 8; nt++) {
            int r0 = bm + wm * 64 + mt * 16 + (lane >> 2);
            int c  = bn + wn * 64 + nt * 8 + (lane & 3) * 2;
            float b0 = __ldg(bias + c);
            float b1 = __ldg(bias + c + 1);
            float2 v0 = make_float2(acc[mt][nt][0] * s + b0, acc[mt][nt][1] * s + b1);
            float2 v1 = make_float2(acc[mt][nt][2] * s + b0, acc[mt][nt][3] * s + b1);
            *reinterpret_cast<float2*>(out + (size_t)r0 * OUTF + c) = v0;
            *reinterpret_cast<float2*>(out + (size_t)(r0 + 8) * OUTF + c) = v1;
        }
    }
}

// ---------------------------------------------------------------------------
extern "C" void kernel_launch(void* const* d_in, const int* in_sizes, int n_in,
                              void* d_out, int out_size) {
    const float* x     = (const float*)d_in[0];
    const void*  wq    = d_in[1];
    const float* scale = (const float*)d_in[2];
    const float* bias  = (const float*)d_in[3];
    float*       out   = (float*)d_out;

    detect_w_kernel<<<1, 256>>>((const int*)wq);
    convert_w_kernel<<<(unsigned)((size_t)OUTF * INF / 4 / 256), 256>>>(wq);
    convert_x_kernel<<<(unsigned)((size_t)TOKENS * INF / 4 / 256), 256>>>(x);

    cudaFuncSetAttribute(gemm_kernel, cudaFuncAttributeMaxDynamicSharedMemorySize, SMEM_TOTAL);
    dim3 grid(OUTF / BN, TOKENS / BM);
    gemm_kernel<<<grid, 256, SMEM_TOTAL>>>(scale, bias, out);
}

// round 17
// speedup vs baseline: 1.0479x; 1.0479x over previous
#include <cuda_runtime.h>
#include <cuda_fp16.h>
#include <cstdint>

#define TOKENS 8192
#define INF    4096
#define OUTF   4096

// Scratch device globals (no allocations allowed).
__device__ __half g_Wh[(size_t)OUTF * INF];    // 32 MB
__device__ __half g_Xh[(size_t)TOKENS * INF];  // 64 MB
__device__ int g_w_is_i8;

// ---------------------------------------------------------------------------
// mbarrier helpers (plain sm_80/sm_90 PTX — legal under compute_100)
// ---------------------------------------------------------------------------
#define MBAR_INIT(a, n) \
    asm volatile("mbarrier.init.shared.b64 [%0], %1;" :: "r"(a), "r"(n) : "memory")
#define MBAR_WAIT(a, ph) do { \
    uint32_t _m = (a), _p = (ph), _d; \
    asm volatile("{ .reg .pred p; mbarrier.try_wait.parity.shared.b64 p, [%1], %2; selp.b32 %0,1,0,p; }" \
                 : "=r"(_d) : "r"(_m), "r"(_p) : "memory"); \
    if (!_d) { \
        asm volatile("{ .reg .pred P; WL_%=: mbarrier.try_wait.parity.shared.b64 P, [%0], %1; " \
                     "@P bra.uni WD_%=; bra.uni WL_%=; WD_%=: }" :: "r"(_m), "r"(_p) : "memory"); \
    } } while (0)
#define MBAR_ARRIVE(a) \
    asm volatile("{ .reg .b64 t; mbarrier.arrive.shared.b64 t, [%0]; }" :: "r"(a) : "memory")
#define CPASYNC_MBAR_ARRIVE_NOINC(a) \
    asm volatile("cp.async.mbarrier.arrive.noinc.shared.b64 [%0];" :: "r"(a) : "memory")

// ---------------------------------------------------------------------------
// Preprocess 0: weight dtype detection (int8 vs int32 delivery)
// ---------------------------------------------------------------------------
__global__ void detect_w_kernel(const int* __restrict__ w32) {
    __shared__ int bad;
    if (threadIdx.x == 0) bad = 0;
    __syncthreads();
    for (int i = threadIdx.x; i < 4096; i += 256) {
        int v = w32[(size_t)i * 1000 + 3];
        if (v < -2 || v > 1) bad = 1;
    }
    __syncthreads();
    if (threadIdx.x == 0) g_w_is_i8 = bad;
}

// ---------------------------------------------------------------------------
// Preprocess 1: weights {-2,-1,0,1} (int8 OR int32) -> fp16 (exact)
// ---------------------------------------------------------------------------
__global__ void convert_w_kernel(const void* __restrict__ wq) {
    size_t i = (size_t)blockIdx.x * blockDim.x + threadIdx.x;
    size_t total4 = (size_t)OUTF * INF / 4;
    if (i >= total4) return;
    int v0, v1, v2, v3;
    if (g_w_is_i8) {
        char4 v = reinterpret_cast<const char4*>(wq)[i];
        v0 = v.x; v1 = v.y; v2 = v.z; v3 = v.w;
    } else {
        int4 v = reinterpret_cast<const int4*>(wq)[i];
        v0 = v.x; v1 = v.y; v2 = v.z; v3 = v.w;
    }
    __half2 p0, p1;
    p0.x = __float2half_rn((float)v0); p0.y = __float2half_rn((float)v1);
    p1.x = __float2half_rn((float)v2); p1.y = __float2half_rn((float)v3);
    reinterpret_cast<__half2*>(g_Wh)[i * 2 + 0] = p0;
    reinterpret_cast<__half2*>(g_Wh)[i * 2 + 1] = p1;
}

// ---------------------------------------------------------------------------
// Preprocess 2: fp32 x -> fp16
// ---------------------------------------------------------------------------
__global__ void convert_x_kernel(const float* __restrict__ x) {
    size_t i = (size_t)blockIdx.x * blockDim.x + threadIdx.x;
    size_t total4 = (size_t)TOKENS * INF / 4;
    if (i >= total4) return;
    float4 v = reinterpret_cast<const float4*>(x)[i];
    __half2 p0, p1;
    p0.x = __float2half_rn(v.x); p0.y = __float2half_rn(v.y);
    p1.x = __float2half_rn(v.z); p1.y = __float2half_rn(v.w);
    reinterpret_cast<__half2*>(g_Xh)[i * 2 + 0] = p0;
    reinterpret_cast<__half2*>(g_Xh)[i * 2 + 1] = p1;
}

// ---------------------------------------------------------------------------
// GEMM: C = Xh @ Wh^T + epilogue.  BM=256 BN=128 BK=64, 256 thr, 1 CTA/SM.
// R14 structure exactly (mbarrier full/empty pipeline, early producer wait,
// refill spread through the ks loop, frag double-buffer, ks-stagger), with
// FOUR stages: the refill-target stage was consumed 2 iterations ago, so
// the producer's empty-wait is always a fast-path, never a convoy.
// ---------------------------------------------------------------------------
#define BM 256
#define BN 128
#define BK 64
#define KT (INF / BK)        // 64 outer iterations
#define STAGES 4
#define PB   144             // smem row pitch bytes
#define A_STG (BM * PB)      // 36864
#define B_STG (BN * PB)      // 18432
#define STG   (A_STG + B_STG)              // 55296
#define BAR_OFF (STAGES * STG)             // barrier area
#define SMEM_TOTAL (BAR_OFF + 64)          // 221248 B

// Issue 3 of the 12 per-thread cp.asyncs for this chunk (part j of 4).
__device__ __forceinline__ void load_part(uint32_t sbase,
                                          const __half* Ag, const __half* Bg,
                                          int kt, int stage, int tid, int j) {
    const int kk = kt * BK;
    const uint32_t d0 = sbase + stage * STG;
#pragma unroll
    for (int q = 0; q < 3; q++) {
        int i = j * 3 + q;
        int c = tid + i * 256;
        const void* src;
        uint32_t dst;
        if (i < 8) {                         // A: 256 rows x 8 segs = 2048 chunks
            int row = c >> 3, seg = c & 7;
            src = Ag + (size_t)row * INF + kk + seg * 8;
            dst = d0 + row * PB + seg * 16;
        } else {                             // B: 128 rows x 8 segs = 1024 chunks
            int o = c - 2048;
            int row = o >> 3, seg = o & 7;
            src = Bg + (size_t)row * INF + kk + seg * 8;
            dst = d0 + A_STG + row * PB + seg * 16;
        }
        asm volatile("cp.async.cg.shared.global [%0], [%1], 16;\n" :: "r"(dst), "l"(src));
    }
}

// 8-ldmatrix fragment fetch for one ks-slice of one stage.
#define FRAG_FETCH(AF, BF, aB, bB, kOff)                                      \
    do {                                                                      \
        _Pragma("unroll")                                                     \
        for (int mt_ = 0; mt_ < 4; mt_++) {                                   \
            asm volatile(                                                     \
                "ldmatrix.sync.aligned.m8n8.x4.shared.b16 {%0,%1,%2,%3}, [%4];\n" \
                : "=r"((AF)[mt_][0]), "=r"((AF)[mt_][1]),                    \
                  "=r"((AF)[mt_][2]), "=r"((AF)[mt_][3])                     \
                : "r"((aB) + (uint32_t)(mt_ * 16) * PB + (kOff)));           \
        }                                                                     \
        _Pragma("unroll")                                                     \
        for (int np_ = 0; np_ < 4; np_++) {                                   \
            asm volatile(                                                     \
                "ldmatrix.sync.aligned.m8n8.x4.shared.b16 {%0,%1,%2,%3}, [%4];\n" \
                : "=r"((BF)[np_ * 2][0]), "=r"((BF)[np_ * 2][1]),            \
                  "=r"((BF)[np_ * 2 + 1][0]), "=r"((BF)[np_ * 2 + 1][1])     \
                : "r"((bB) + (uint32_t)(np_ * 16) * PB + (kOff)));           \
        }                                                                     \
    } while (0)

__global__ __launch_bounds__(256, 1) void gemm_kernel(const float* __restrict__ scale_p,
                                                      const float* __restrict__ bias,
                                                      float* __restrict__ out) {
    extern __shared__ char smem[];
    uint32_t sbase;
    asm("{ .reg .u64 t; cvta.to.shared.u64 t, %1; cvt.u32.u64 %0, t; }"
        : "=r"(sbase) : "l"(smem));

    const int tid  = threadIdx.x;
    const int warp = tid >> 5;
    const int lane = tid & 31;
    const int wm   = warp >> 1;      // 4 m-warps: 64 rows each
    const int wn   = warp & 1;       // 2 n-warps: 64 cols each
    const int koff = (warp & 4) ? 2 : 0;   // ks stagger: warps 4-7 rotate by 2
    const int bm   = blockIdx.y * BM;
    const int bn   = blockIdx.x * BN;

    // full(s) at BAR_OFF + s*16, empty(s) at +8 (both count 256)
    const uint32_t barB = sbase + BAR_OFF;
    if (tid == 0) {
#pragma unroll
        for (int s = 0; s < STAGES; s++) {
            MBAR_INIT(barB + s * 16, 256u);
            MBAR_INIT(barB + s * 16 + 8, 256u);
        }
    }
    __syncthreads();   // only barrier: after init

    const __half* Ag = g_Xh + (size_t)bm * INF;
    const __half* Bg = g_Wh + (size_t)bn * INF;

    const uint32_t aRowOff = (uint32_t)(wm * 64 + (lane & 15)) * PB + ((lane >> 4) << 3) * 2;
    const uint32_t bRowOff = (uint32_t)(wn * 64 + ((lane >> 4) << 3) + (lane & 7)) * PB
                             + (((lane >> 3) & 1) << 3) * 2;

    float acc[4][8][4];
#pragma unroll
    for (int mt = 0; mt < 4; mt++)
#pragma unroll
        for (int nt = 0; nt < 8; nt++)
#pragma unroll
            for (int r = 0; r < 4; r++) acc[mt][nt][r] = 0.0f;

    uint32_t af[2][4][4];
    uint32_t bf[2][8][2];
    uint32_t phF = 0, phE = 0;   // per-stage parity bits

    // Prologue: stages 0,1 <- chunks 0,1 (fresh stages, no empty wait)
#pragma unroll
    for (int j = 0; j < 4; j++) load_part(sbase, Ag, Bg, 0, 0, tid, j);
    CPASYNC_MBAR_ARRIVE_NOINC(barB + 0 * 16);
#pragma unroll
    for (int j = 0; j < 4; j++) load_part(sbase, Ag, Bg, 1, 1, tid, j);
    CPASYNC_MBAR_ARRIVE_NOINC(barB + 1 * 16);

#pragma unroll 1
    for (int kt = 0; kt < KT; kt++) {
        const int s = kt % STAGES;
        MBAR_WAIT(barB + s * 16, (phF >> s) & 1);
        phF ^= 1u << s;

        const uint32_t aBase = sbase + s * STG + aRowOff;
        const uint32_t bBase = sbase + s * STG + A_STG + bRowOff;

        const bool doLoad = (kt + 2 < KT);
        const int ls = (kt + 2) % STAGES;

        // First fragment load: ks index rotated per warp half.
        {
            const uint32_t kOff = (uint32_t)((koff & 3) * 16) * 2;
            FRAG_FETCH(af[0], bf[0], aBase, bBase, kOff);
        }

        // Producer: wait for the stage we are about to overwrite to be empty.
        // With 4 stages it was consumed at kt-2 — this wait is a fast-path.
        // (Stages 2,3 are fresh at kt=0,1: no wait needed.)
        if (doLoad && kt >= 2) {
            MBAR_WAIT(barB + ls * 16 + 8, (phE >> ls) & 1);
            phE ^= 1u << ls;
        }

#pragma unroll
        for (int j = 0; j < 4; j++) {
            const int cur = j & 1;
            const int nxt = cur ^ 1;
            if (j < 3) {
                const uint32_t kOff = (uint32_t)(((j + 1 + koff) & 3) * 16) * 2;
                FRAG_FETCH(af[nxt], bf[nxt], aBase, bBase, kOff);
            }
            if (doLoad) {
                load_part(sbase, Ag, Bg, kt + 2, ls, tid, j);
                if (j == 3) CPASYNC_MBAR_ARRIVE_NOINC(barB + ls * 16);
            }
#pragma unroll
            for (int mt = 0; mt < 4; mt++)
#pragma unroll
                for (int nt = 0; nt < 8; nt++) {
                    asm volatile(
                        "mma.sync.aligned.m16n8k16.row.col.f32.f16.f16.f32 "
                        "{%0,%1,%2,%3}, {%4,%5,%6,%7}, {%8,%9}, {%0,%1,%2,%3};\n"
                        : "+f"(acc[mt][nt][0]), "+f"(acc[mt][nt][1]),
                          "+f"(acc[mt][nt][2]), "+f"(acc[mt][nt][3])
                        : "r"(af[cur][mt][0]), "r"(af[cur][mt][1]),
                          "r"(af[cur][mt][2]), "r"(af[cur][mt][3]),
                          "r"(bf[cur][nt][0]), "r"(bf[cur][nt][1]));
                }
        }

        // Consumer: this stage's reads are done; signal empty.  Stage s is
        // refilled (for chunk kt+4) at iteration kt+2, which loads only if
        // kt+4 < KT.
        if (kt + 4 < KT) {
            MBAR_ARRIVE(barB + s * 16 + 8);
        }
    }

    // Epilogue: y = scale * acc + bias
    const float s = __ldg(scale_p);
#pragma unroll
    for (int mt = 0; mt < 4; mt++) {
#pragma unroll
        for (int nt = 0; nt < 8; nt++) {
            int r0 = bm + wm * 64 + mt * 16 + (lane >> 2);
            int c  = bn + wn * 64 + nt * 8 + (lane & 3) * 2;
            float b0 = __ldg(bias + c);
            float b1 = __ldg(bias + c + 1);
            float2 v0 = make_float2(acc[mt][nt][0] * s + b0, acc[mt][nt][1] * s + b1);
            float2 v1 = make_float2(acc[mt][nt][2] * s + b0, acc[mt][nt][3] * s + b1);
            *reinterpret_cast<float2*>(out + (size_t)r0 * OUTF + c) = v0;
            *reinterpret_cast<float2*>(out + (size_t)(r0 + 8) * OUTF + c) = v1;
        }
    }
}

// ---------------------------------------------------------------------------
extern "C" void kernel_launch(void* const* d_in, const int* in_sizes, int n_in,
                              void* d_out, int out_size) {
    const float* x     = (const float*)d_in[0];
    const void*  wq    = d_in[1];
    const float* scale = (const float*)d_in[2];
    const float* bias  = (const float*)d_in[3];
    float*       out   = (float*)d_out;

    detect_w_kernel<<<1, 256>>>((const int*)wq);
    convert_w_kernel<<<(unsigned)((size_t)OUTF * INF / 4 / 256), 256>>>(wq);
    convert_x_kernel<<<(unsigned)((size_t)TOKENS * INF / 4 / 256), 256>>>(x);

    cudaFuncSetAttribute(gemm_kernel, cudaFuncAttributeMaxDynamicSharedMemorySize, SMEM_TOTAL);
    dim3 grid(OUTF / BN, TOKENS / BM);
    gemm_kernel<<<grid, 256, SMEM_TOTAL>>>(scale, bias, out);
}